// round 2
// baseline (speedup 1.0000x reference)
#include <cuda_runtime.h>
#include <math.h>

#define B_      4096
#define SEQ_    59
#define FEAT_   64
#define U_      1024
#define VOCAB_  578
#define NPAD    640
#define KTOT    1088            // U_ + FEAT_
#define N4U     4096            // 4*U_
#define XROW    (SEQ_*FEAT_)    // per-batch row stride of x

// ---------------- device scratch (no allocations allowed) ----------------
__device__ float g_Wp[KTOT * N4U];       // permuted [rec; kernel], cols n=4u+g
__device__ float g_biasp[N4U];           // permuted bias
__device__ float g_h[2][B_ * U_];        // double-buffered hidden state
__device__ float g_c[B_ * U_];           // cell state (in-place)
__device__ float g_w2p[U_ * NPAD];       // w2 padded to 640 cols
__device__ float g_b2p[NPAD];
__device__ float g_logits[B_ * NPAD];

// ---------------- weight permutation (runs every launch; ~trivial) -------
__global__ void permute_weights(const float* __restrict__ kernel,
                                const float* __restrict__ rec_kernel,
                                const float* __restrict__ bias,
                                const float* __restrict__ w2,
                                const float* __restrict__ b2) {
    int stride = gridDim.x * blockDim.x;
    int idx = blockIdx.x * blockDim.x + threadIdx.x;

    // W' [KTOT][4096]: col n = 4u+g  <-  source col g*U + u
    for (int i = idx; i < KTOT * N4U; i += stride) {
        int k = i >> 12;            // / 4096
        int n = i & 4095;
        int u = n >> 2, g = n & 3;
        int src = g * U_ + u;
        g_Wp[i] = (k < U_) ? rec_kernel[k * N4U + src]
                           : kernel[(k - U_) * N4U + src];
    }
    for (int n = idx; n < N4U; n += stride) {
        int u = n >> 2, g = n & 3;
        g_biasp[n] = bias[g * U_ + u];
    }
    for (int i = idx; i < U_ * NPAD; i += stride) {
        int k = i / NPAD, v = i - k * NPAD;
        g_w2p[i] = (v < VOCAB_) ? w2[k * VOCAB_ + v] : 0.f;
    }
    for (int v = idx; v < NPAD; v += stride)
        g_b2p[v] = (v < VOCAB_) ? b2[v] : 0.f;
}

__global__ void zero_state() {
    int stride = gridDim.x * blockDim.x;
    int idx = blockIdx.x * blockDim.x + threadIdx.x;
    for (int i = idx; i < B_ * U_; i += stride) {
        g_h[0][i] = 0.f;
        g_c[i]    = 0.f;
    }
}

__device__ __forceinline__ float sigmoidf_(float x) {
    return 1.f / (1.f + expf(-x));
}

// ---------------- fused LSTM step: Z = [h|x_t] @ W' ; gates in epilogue ---
// 128x128 tile, K-tile 8, 256 threads, 8x8 per-thread microtile.
__global__ void __launch_bounds__(256, 2)
lstm_step(const float* __restrict__ x, int t, int hin_idx) {
    const float* __restrict__ hin = g_h[hin_idx];
    float* __restrict__ hout = g_h[hin_idx ^ 1];

    __shared__ __align__(16) float As[8][128];   // A tile transposed: As[k][m]
    __shared__ __align__(16) float Bs[8][128];   // B tile: Bs[k][n]

    const int tid = threadIdx.x;
    const int tx = tid & 15;       // 16 threads in N
    const int ty = tid >> 4;       // 16 threads in M
    const int mbase = blockIdx.y * 128;
    const int nbase = blockIdx.x * 128;

    float acc[8][8];
    #pragma unroll
    for (int i = 0; i < 8; i++)
        #pragma unroll
        for (int j = 0; j < 8; j++) acc[i][j] = 0.f;

    const int arow = tid >> 1;            // 0..127
    const int acol = (tid & 1) << 2;      // 0 or 4
    const int brow = tid >> 5;            // 0..7
    const int bcol = (tid & 31) << 2;     // 0..124

    for (int k0 = 0; k0 < KTOT; k0 += 8) {
        // ---- load A tile (128 x 8), transposed into As[k][m]
        int grow = mbase + arow;
        int gk = k0 + acol;
        float4 av;
        if (gk < U_) {
            av = *reinterpret_cast<const float4*>(hin + (size_t)grow * U_ + gk);
        } else {
            av = *reinterpret_cast<const float4*>(
                x + (size_t)grow * XROW + t * FEAT_ + (gk - U_));
        }
        As[acol + 0][arow] = av.x;
        As[acol + 1][arow] = av.y;
        As[acol + 2][arow] = av.z;
        As[acol + 3][arow] = av.w;

        // ---- load B tile (8 x 128)
        float4 bv = *reinterpret_cast<const float4*>(
            g_Wp + (size_t)(k0 + brow) * N4U + nbase + bcol);
        *reinterpret_cast<float4*>(&Bs[brow][bcol]) = bv;

        __syncthreads();

        #pragma unroll
        for (int kk = 0; kk < 8; kk++) {
            float a[8], b[8];
            const float4* Av = reinterpret_cast<const float4*>(&As[kk][ty * 8]);
            const float4* Bv = reinterpret_cast<const float4*>(&Bs[kk][tx * 8]);
            float4 a0 = Av[0], a1 = Av[1];
            float4 b0 = Bv[0], b1 = Bv[1];
            a[0]=a0.x; a[1]=a0.y; a[2]=a0.z; a[3]=a0.w;
            a[4]=a1.x; a[5]=a1.y; a[6]=a1.z; a[7]=a1.w;
            b[0]=b0.x; b[1]=b0.y; b[2]=b0.z; b[3]=b0.w;
            b[4]=b1.x; b[5]=b1.y; b[6]=b1.z; b[7]=b1.w;
            #pragma unroll
            for (int i = 0; i < 8; i++)
                #pragma unroll
                for (int j = 0; j < 8; j++)
                    acc[i][j] = fmaf(a[i], b[j], acc[i][j]);
        }
        __syncthreads();
    }

    // ---- epilogue: per-thread cols are [tx*8, tx*8+8) = 2 u's x 4 gates
    #pragma unroll
    for (int i = 0; i < 8; i++) {
        int b_idx = mbase + ty * 8 + i;
        #pragma unroll
        for (int uu = 0; uu < 2; uu++) {
            int n0 = nbase + tx * 8 + uu * 4;   // gate-0 column; n0 % 4 == 0
            int u = n0 >> 2;
            float zi = acc[i][uu * 4 + 0] + g_biasp[n0 + 0];
            float zf = acc[i][uu * 4 + 1] + g_biasp[n0 + 1];
            float zg = acc[i][uu * 4 + 2] + g_biasp[n0 + 2];
            float zo = acc[i][uu * 4 + 3] + g_biasp[n0 + 3];
            float ig = sigmoidf_(zi);
            float fg = sigmoidf_(zf);
            float gg = tanhf(zg);
            float og = sigmoidf_(zo);
            size_t cidx = (size_t)b_idx * U_ + u;
            float cn = fg * g_c[cidx] + ig * gg;
            g_c[cidx]  = cn;
            hout[cidx] = og * tanhf(cn);
        }
    }
}

// ---------------- final dense: logits = h_last @ w2p + b2p ---------------
__global__ void __launch_bounds__(256, 2)
dense2(int h_idx) {
    const float* __restrict__ A = g_h[h_idx];

    __shared__ __align__(16) float As[8][128];
    __shared__ __align__(16) float Bs[8][128];

    const int tid = threadIdx.x;
    const int tx = tid & 15;
    const int ty = tid >> 4;
    const int mbase = blockIdx.y * 128;
    const int nbase = blockIdx.x * 128;

    float acc[8][8];
    #pragma unroll
    for (int i = 0; i < 8; i++)
        #pragma unroll
        for (int j = 0; j < 8; j++) acc[i][j] = 0.f;

    const int arow = tid >> 1;
    const int acol = (tid & 1) << 2;
    const int brow = tid >> 5;
    const int bcol = (tid & 31) << 2;

    for (int k0 = 0; k0 < U_; k0 += 8) {
        int grow = mbase + arow;
        float4 av = *reinterpret_cast<const float4*>(
            A + (size_t)grow * U_ + k0 + acol);
        As[acol + 0][arow] = av.x;
        As[acol + 1][arow] = av.y;
        As[acol + 2][arow] = av.z;
        As[acol + 3][arow] = av.w;

        float4 bv = *reinterpret_cast<const float4*>(
            g_w2p + (size_t)(k0 + brow) * NPAD + nbase + bcol);
        *reinterpret_cast<float4*>(&Bs[brow][bcol]) = bv;

        __syncthreads();

        #pragma unroll
        for (int kk = 0; kk < 8; kk++) {
            float a[8], b[8];
            const float4* Av = reinterpret_cast<const float4*>(&As[kk][ty * 8]);
            const float4* Bv = reinterpret_cast<const float4*>(&Bs[kk][tx * 8]);
            float4 a0 = Av[0], a1 = Av[1];
            float4 b0 = Bv[0], b1 = Bv[1];
            a[0]=a0.x; a[1]=a0.y; a[2]=a0.z; a[3]=a0.w;
            a[4]=a1.x; a[5]=a1.y; a[6]=a1.z; a[7]=a1.w;
            b[0]=b0.x; b[1]=b0.y; b[2]=b0.z; b[3]=b0.w;
            b[4]=b1.x; b[5]=b1.y; b[6]=b1.z; b[7]=b1.w;
            #pragma unroll
            for (int i = 0; i < 8; i++)
                #pragma unroll
                for (int j = 0; j < 8; j++)
                    acc[i][j] = fmaf(a[i], b[j], acc[i][j]);
        }
        __syncthreads();
    }

    #pragma unroll
    for (int i = 0; i < 8; i++) {
        int b_idx = mbase + ty * 8 + i;
        #pragma unroll
        for (int j = 0; j < 8; j++) {
            int n = nbase + tx * 8 + j;
            g_logits[(size_t)b_idx * NPAD + n] = acc[i][j] + g_b2p[n];
        }
    }
}

// ---------------- softmax over 578 logits per batch row -------------------
__global__ void softmax_kernel(float* __restrict__ out) {
    const int b = blockIdx.x;
    const float* __restrict__ l = g_logits + (size_t)b * NPAD;
    __shared__ float red[256];
    const int tid = threadIdx.x;

    float m = -1e30f;
    for (int v = tid; v < VOCAB_; v += 256) m = fmaxf(m, l[v]);
    red[tid] = m;
    __syncthreads();
    for (int s = 128; s > 0; s >>= 1) {
        if (tid < s) red[tid] = fmaxf(red[tid], red[tid + s]);
        __syncthreads();
    }
    float mx = red[0];
    __syncthreads();

    float sum = 0.f;
    for (int v = tid; v < VOCAB_; v += 256) sum += expf(l[v] - mx);
    red[tid] = sum;
    __syncthreads();
    for (int s = 128; s > 0; s >>= 1) {
        if (tid < s) red[tid] += red[tid + s];
        __syncthreads();
    }
    float inv = 1.f / red[0];

    for (int v = tid; v < VOCAB_; v += 256)
        out[(size_t)b * VOCAB_ + v] = expf(l[v] - mx) * inv;
}

// ---------------- launch --------------------------------------------------
extern "C" void kernel_launch(void* const* d_in, const int* in_sizes, int n_in,
                              void* d_out, int out_size) {
    const float* x      = (const float*)d_in[0];
    const float* kernel = (const float*)d_in[1];
    const float* rec    = (const float*)d_in[2];
    const float* bias   = (const float*)d_in[3];
    const float* w2     = (const float*)d_in[4];
    const float* b2     = (const float*)d_in[5];
    float* out = (float*)d_out;

    permute_weights<<<2048, 256>>>(kernel, rec, bias, w2, b2);
    zero_state<<<2048, 256>>>();

    dim3 grid(N4U / 128, B_ / 128);   // 32 x 32
    for (int s = 0; s < SEQ_; s++)
        lstm_step<<<grid, 256>>>(x, s, s & 1);

    dense2<<<dim3(NPAD / 128, B_ / 128), 256>>>(SEQ_ & 1);
    softmax_kernel<<<B_, 256>>>(out);
}

// round 4
// speedup vs baseline: 3.0215x; 3.0215x over previous
#include <cuda_runtime.h>
#include <cuda_bf16.h>
#include <math.h>
#include <stdint.h>

#define B_      4096
#define SEQ_    59
#define FEAT_   64
#define U_      1024
#define VOCAB_  578
#define NPAD    640
#define KTOT    1088            // U_ + FEAT_
#define N4U     4096            // 4*U_
#define XROW    (SEQ_*FEAT_)

#define KBLK        64
#define NKB         17          // KTOT / KBLK
#define NSTAGE      3
#define STAGE_BYTES 65536       // Ahi 16K | Alo 16K | Bhi 16K | Blo 16K
#define SMEM_BYTES  (NSTAGE * STAGE_BYTES)   // 196608

// ---------------- device scratch ----------------
__device__ __nv_bfloat16 g_Wt_hi[(size_t)N4U * KTOT];   // [n][k], n = 4u+g permuted
__device__ __nv_bfloat16 g_Wt_lo[(size_t)N4U * KTOT];
__device__ float         g_biasp[N4U];
__device__ __nv_bfloat16 g_h_hi[2][(size_t)B_ * U_];
__device__ __nv_bfloat16 g_h_lo[2][(size_t)B_ * U_];
__device__ float         g_c[(size_t)B_ * U_];
__device__ __nv_bfloat16 g_x_hi[(size_t)SEQ_ * B_ * FEAT_]; // [t][b][f]
__device__ __nv_bfloat16 g_x_lo[(size_t)SEQ_ * B_ * FEAT_];
__device__ float         g_w2p[U_ * NPAD];
__device__ float         g_b2p[NPAD];
__device__ float         g_logits[(size_t)B_ * NPAD];

// ---------------- helpers ----------------
__device__ __forceinline__ uint32_t s2u(const void* p) {
    uint32_t a;
    asm("{ .reg .u64 t; cvta.to.shared.u64 t, %1; cvt.u32.u64 %0, t; }"
        : "=r"(a) : "l"(p));
    return a;
}
__device__ __forceinline__ void cp16(uint32_t saddr, const void* g) {
    asm volatile("cp.async.cg.shared.global [%0], [%1], 16;"
                 :: "r"(saddr), "l"(g));
}
__device__ __forceinline__ void ldmx4(uint32_t* r, uint32_t addr) {
    asm volatile("ldmatrix.sync.aligned.m8n8.x4.shared.b16 {%0,%1,%2,%3}, [%4];"
                 : "=r"(r[0]), "=r"(r[1]), "=r"(r[2]), "=r"(r[3]) : "r"(addr));
}
__device__ __forceinline__ void mma_bf16(float* d, const uint32_t* a,
                                         const uint32_t* b) {
    asm volatile(
        "mma.sync.aligned.m16n8k16.row.col.f32.bf16.bf16.f32 "
        "{%0,%1,%2,%3}, {%4,%5,%6,%7}, {%8,%9}, {%0,%1,%2,%3};"
        : "+f"(d[0]), "+f"(d[1]), "+f"(d[2]), "+f"(d[3])
        : "r"(a[0]), "r"(a[1]), "r"(a[2]), "r"(a[3]), "r"(b[0]), "r"(b[1]));
}
#define SWZ(o) ((o) ^ (((o) >> 3) & 0x70))

// ---------------- prep kernels ----------------
__global__ void prep_weights(const float* __restrict__ kernel,
                             const float* __restrict__ rec,
                             const float* __restrict__ bias,
                             const float* __restrict__ w2,
                             const float* __restrict__ b2) {
    int stride = gridDim.x * blockDim.x;
    int idx = blockIdx.x * blockDim.x + threadIdx.x;
    for (size_t i = idx; i < (size_t)N4U * KTOT; i += stride) {
        int n = (int)(i / KTOT), k = (int)(i % KTOT);
        int u = n >> 2, g = n & 3;
        int src = g * U_ + u;
        float v = (k < U_) ? rec[(size_t)k * N4U + src]
                           : kernel[(size_t)(k - U_) * N4U + src];
        __nv_bfloat16 h = __float2bfloat16(v);
        g_Wt_hi[i] = h;
        g_Wt_lo[i] = __float2bfloat16(v - __bfloat162float(h));
    }
    for (int n = idx; n < N4U; n += stride) {
        int u = n >> 2, g = n & 3;
        g_biasp[n] = bias[g * U_ + u];
    }
    for (int i = idx; i < U_ * NPAD; i += stride) {
        int k = i / NPAD, v = i - k * NPAD;
        g_w2p[i] = (v < VOCAB_) ? w2[k * VOCAB_ + v] : 0.f;
    }
    for (int v = idx; v < NPAD; v += stride)
        g_b2p[v] = (v < VOCAB_) ? b2[v] : 0.f;
}

__global__ void prep_x(const float* __restrict__ x) {
    int stride = gridDim.x * blockDim.x;
    int idx = blockIdx.x * blockDim.x + threadIdx.x;
    for (size_t i = idx; i < (size_t)SEQ_ * B_ * FEAT_; i += stride) {
        int t = (int)(i / ((size_t)B_ * FEAT_));
        int r = (int)((i / FEAT_) % B_);
        int f = (int)(i % FEAT_);
        float v = x[(size_t)r * XROW + t * FEAT_ + f];
        __nv_bfloat16 h = __float2bfloat16(v);
        g_x_hi[i] = h;
        g_x_lo[i] = __float2bfloat16(v - __bfloat162float(h));
    }
}

__global__ void zero_state() {
    int stride = gridDim.x * blockDim.x;
    int idx = blockIdx.x * blockDim.x + threadIdx.x;
    const __nv_bfloat16 z = __float2bfloat16(0.f);
    for (size_t i = idx; i < (size_t)B_ * U_; i += stride) {
        g_h_hi[0][i] = z;
        g_h_lo[0][i] = z;
        g_c[i] = 0.f;
    }
}

// ---------------- fused LSTM step: mma.sync bf16 3-pass split ----------------
// CTA 128x128, 8 warps (2M x 4N), warp tile 64x32, K-chunk 64, 3-stage cp.async.
__global__ void __launch_bounds__(256, 1)
lstm_step_mma(int t, int hin) {
    extern __shared__ __align__(1024) char smem[];
    const uint32_t sb = s2u(smem);
    const int tid = threadIdx.x;
    const int lane = tid & 31, wid = tid >> 5;
    const int wm = wid & 1, wn = wid >> 1;
    const int mbase = blockIdx.y * 128;
    const int nbase = blockIdx.x * 128;

    const __nv_bfloat16* __restrict__ hh = g_h_hi[hin];
    const __nv_bfloat16* __restrict__ hl = g_h_lo[hin];
    __nv_bfloat16* __restrict__ oh = g_h_hi[hin ^ 1];
    __nv_bfloat16* __restrict__ ol = g_h_lo[hin ^ 1];

    float acc[4][4][4];
    #pragma unroll
    for (int i = 0; i < 4; i++)
        #pragma unroll
        for (int j = 0; j < 4; j++)
            #pragma unroll
            for (int q = 0; q < 4; q++) acc[i][j][q] = 0.f;

    auto loadStage = [&](int s, int kb) {
        const uint32_t base = sb + s * STAGE_BYTES;
        #pragma unroll
        for (int it = 0; it < 4; it++) {
            int idx = tid + it * 256;
            int row = idx >> 3, cc = idx & 7;
            uint32_t sw = SWZ((uint32_t)(row * 128 + cc * 16));
            const __nv_bfloat16 *gah, *gal;
            if (kb < 16) {
                size_t o = (size_t)(mbase + row) * U_ + kb * KBLK + cc * 8;
                gah = hh + o; gal = hl + o;
            } else {
                size_t o = ((size_t)t * B_ + mbase + row) * FEAT_ + cc * 8;
                gah = g_x_hi + o; gal = g_x_lo + o;
            }
            cp16(base + sw, gah);
            cp16(base + 16384 + sw, gal);
            size_t ob = (size_t)(nbase + row) * KTOT + kb * KBLK + cc * 8;
            cp16(base + 32768 + sw, g_Wt_hi + ob);
            cp16(base + 49152 + sw, g_Wt_lo + ob);
        }
        asm volatile("cp.async.commit_group;" ::: "memory");
    };

    loadStage(0, 0);
    loadStage(1, 1);
    loadStage(2, 2);

    for (int kb = 0; kb < NKB; kb++) {
        const int s = kb % 3;
        if (kb < 15)       asm volatile("cp.async.wait_group 2;" ::: "memory");
        else if (kb == 15) asm volatile("cp.async.wait_group 1;" ::: "memory");
        else               asm volatile("cp.async.wait_group 0;" ::: "memory");
        __syncthreads();

        const uint32_t Ah = sb + s * STAGE_BYTES;
        const uint32_t Al = Ah + 16384;
        const uint32_t Bh = Ah + 32768;
        const uint32_t Bl = Ah + 49152;

        #pragma unroll
        for (int kk = 0; kk < 4; kk++) {
            // ---- A fragments (4 m16 tiles, hi+lo)
            const int arow = wm * 64 + (lane & 15);
            const uint32_t akoff = (uint32_t)(kk * 32 + ((lane >> 4) & 1) * 16);
            uint32_t a_hi[4][4], a_lo[4][4];
            #pragma unroll
            for (int mt = 0; mt < 4; mt++) {
                uint32_t adr = SWZ((uint32_t)((arow + mt * 16) * 128) + akoff);
                ldmx4(a_hi[mt], Ah + adr);
                ldmx4(a_lo[mt], Al + adr);
            }
            // ---- B fragments (4 n8 tiles as 2 x4 loads, hi+lo)
            const int brow = wn * 32 + (lane & 7) + ((lane >> 4) & 1) * 8;
            const uint32_t bkoff = (uint32_t)(kk * 32 + ((lane >> 3) & 1) * 16);
            uint32_t b_hi[2][4], b_lo[2][4];
            #pragma unroll
            for (int np = 0; np < 2; np++) {
                uint32_t adr = SWZ((uint32_t)((brow + np * 16) * 128) + bkoff);
                ldmx4(b_hi[np], Bh + adr);
                ldmx4(b_lo[np], Bl + adr);
            }
            // ---- 3-pass mma
            #pragma unroll
            for (int mt = 0; mt < 4; mt++)
                #pragma unroll
                for (int nt = 0; nt < 4; nt++) {
                    const uint32_t* bh2 = &b_hi[nt >> 1][(nt & 1) * 2];
                    const uint32_t* bl2 = &b_lo[nt >> 1][(nt & 1) * 2];
                    mma_bf16(acc[mt][nt], a_hi[mt], bh2);
                    mma_bf16(acc[mt][nt], a_hi[mt], bl2);
                    mma_bf16(acc[mt][nt], a_lo[mt], bh2);
                }
        }
        __syncthreads();
        if (kb + 3 < NKB) loadStage(s, kb + 3);
    }

    // ---- epilogue: stage accums to smem [128][132], then gate math ----
    float* sf = reinterpret_cast<float*>(smem);
    #pragma unroll
    for (int mt = 0; mt < 4; mt++) {
        int r0 = wm * 64 + mt * 16 + (lane >> 2);
        #pragma unroll
        for (int nt = 0; nt < 4; nt++) {
            int c = wn * 32 + nt * 8 + 2 * (lane & 3);
            sf[r0 * 132 + c]           = acc[mt][nt][0];
            sf[r0 * 132 + c + 1]       = acc[mt][nt][1];
            sf[(r0 + 8) * 132 + c]     = acc[mt][nt][2];
            sf[(r0 + 8) * 132 + c + 1] = acc[mt][nt][3];
        }
    }
    __syncthreads();

    #pragma unroll 1
    for (int it = 0; it < 16; it++) {
        int idx = it * 256 + tid;
        int row = idx >> 5, uu = idx & 31;
        float4 z = *reinterpret_cast<const float4*>(&sf[row * 132 + uu * 4]);
        int n0 = nbase + uu * 4;
        float4 bz = *reinterpret_cast<const float4*>(&g_biasp[n0]);
        float zi = z.x + bz.x;
        float zf = z.y + bz.y;
        float zg = z.z + bz.z;
        float zo = z.w + bz.w;
        float ig = 1.f / (1.f + __expf(-zi));
        float fg = 1.f / (1.f + __expf(-zf));
        float gg = tanhf(zg);
        float og = 1.f / (1.f + __expf(-zo));
        size_t ci = (size_t)(mbase + row) * U_ + (n0 >> 2);
        float cn = fg * g_c[ci] + ig * gg;
        g_c[ci] = cn;
        float hv = og * tanhf(cn);
        __nv_bfloat16 hb = __float2bfloat16(hv);
        oh[ci] = hb;
        ol[ci] = __float2bfloat16(hv - __bfloat162float(hb));
    }
}

// ---------------- final dense (fp32 SGEMM, reads h = hi+lo) ----------------
__global__ void __launch_bounds__(256, 2)
dense2(int h_idx) {
    const __nv_bfloat16* __restrict__ Ah = g_h_hi[h_idx];
    const __nv_bfloat16* __restrict__ Al = g_h_lo[h_idx];

    __shared__ __align__(16) float As[8][128];
    __shared__ __align__(16) float Bs[8][128];

    const int tid = threadIdx.x;
    const int tx = tid & 15, ty = tid >> 4;
    const int mbase = blockIdx.y * 128, nbase = blockIdx.x * 128;

    float acc[8][8];
    #pragma unroll
    for (int i = 0; i < 8; i++)
        #pragma unroll
        for (int j = 0; j < 8; j++) acc[i][j] = 0.f;

    const int arow = tid >> 1, acol = (tid & 1) << 2;
    const int brow = tid >> 5, bcol = (tid & 31) << 2;

    for (int k0 = 0; k0 < U_; k0 += 8) {
        size_t ao = (size_t)(mbase + arow) * U_ + k0 + acol;
        __nv_bfloat162 a01 = *reinterpret_cast<const __nv_bfloat162*>(Ah + ao);
        __nv_bfloat162 a23 = *reinterpret_cast<const __nv_bfloat162*>(Ah + ao + 2);
        __nv_bfloat162 l01 = *reinterpret_cast<const __nv_bfloat162*>(Al + ao);
        __nv_bfloat162 l23 = *reinterpret_cast<const __nv_bfloat162*>(Al + ao + 2);
        As[acol + 0][arow] = __bfloat162float(a01.x) + __bfloat162float(l01.x);
        As[acol + 1][arow] = __bfloat162float(a01.y) + __bfloat162float(l01.y);
        As[acol + 2][arow] = __bfloat162float(a23.x) + __bfloat162float(l23.x);
        As[acol + 3][arow] = __bfloat162float(a23.y) + __bfloat162float(l23.y);

        float4 bv = *reinterpret_cast<const float4*>(
            g_w2p + (size_t)(k0 + brow) * NPAD + nbase + bcol);
        *reinterpret_cast<float4*>(&Bs[brow][bcol]) = bv;

        __syncthreads();
        #pragma unroll
        for (int kk = 0; kk < 8; kk++) {
            float a[8], b[8];
            const float4* Av = reinterpret_cast<const float4*>(&As[kk][ty * 8]);
            const float4* Bv = reinterpret_cast<const float4*>(&Bs[kk][tx * 8]);
            float4 a0 = Av[0], a1 = Av[1], b0 = Bv[0], b1 = Bv[1];
            a[0]=a0.x;a[1]=a0.y;a[2]=a0.z;a[3]=a0.w;a[4]=a1.x;a[5]=a1.y;a[6]=a1.z;a[7]=a1.w;
            b[0]=b0.x;b[1]=b0.y;b[2]=b0.z;b[3]=b0.w;b[4]=b1.x;b[5]=b1.y;b[6]=b1.z;b[7]=b1.w;
            #pragma unroll
            for (int i = 0; i < 8; i++)
                #pragma unroll
                for (int j = 0; j < 8; j++)
                    acc[i][j] = fmaf(a[i], b[j], acc[i][j]);
        }
        __syncthreads();
    }
    #pragma unroll
    for (int i = 0; i < 8; i++) {
        int bi = mbase + ty * 8 + i;
        #pragma unroll
        for (int j = 0; j < 8; j++) {
            int n = nbase + tx * 8 + j;
            g_logits[(size_t)bi * NPAD + n] = acc[i][j] + g_b2p[n];
        }
    }
}

// ---------------- softmax ----------------
__global__ void softmax_kernel(float* __restrict__ out) {
    const int b = blockIdx.x;
    const float* __restrict__ l = g_logits + (size_t)b * NPAD;
    __shared__ float red[256];
    const int tid = threadIdx.x;

    float mval = -1e30f;
    for (int v = tid; v < VOCAB_; v += 256) mval = fmaxf(mval, l[v]);
    red[tid] = mval;
    __syncthreads();
    for (int s = 128; s > 0; s >>= 1) {
        if (tid < s) red[tid] = fmaxf(red[tid], red[tid + s]);
        __syncthreads();
    }
    float mx = red[0];
    __syncthreads();

    float sum = 0.f;
    for (int v = tid; v < VOCAB_; v += 256) sum += expf(l[v] - mx);
    red[tid] = sum;
    __syncthreads();
    for (int s = 128; s > 0; s >>= 1) {
        if (tid < s) red[tid] += red[tid + s];
        __syncthreads();
    }
    float inv = 1.f / red[0];
    for (int v = tid; v < VOCAB_; v += 256)
        out[(size_t)b * VOCAB_ + v] = expf(l[v] - mx) * inv;
}

// ---------------- launch ----------------
extern "C" void kernel_launch(void* const* d_in, const int* in_sizes, int n_in,
                              void* d_out, int out_size) {
    const float* x      = (const float*)d_in[0];
    const float* kernel = (const float*)d_in[1];
    const float* rec    = (const float*)d_in[2];
    const float* bias   = (const float*)d_in[3];
    const float* w2     = (const float*)d_in[4];
    const float* b2     = (const float*)d_in[5];
    float* out = (float*)d_out;

    cudaFuncSetAttribute(lstm_step_mma,
                         cudaFuncAttributeMaxDynamicSharedMemorySize, SMEM_BYTES);

    prep_weights<<<2048, 256>>>(kernel, rec, bias, w2, b2);
    prep_x<<<2048, 256>>>(x);
    zero_state<<<2048, 256>>>();

    dim3 grid(N4U / 128, B_ / 128);   // 32 x 32
    for (int s = 0; s < SEQ_; s++)
        lstm_step_mma<<<grid, 256, SMEM_BYTES>>>(s, s & 1);

    dense2<<<dim3(NPAD / 128, B_ / 128), 256>>>(SEQ_ & 1);
    softmax_kernel<<<B_, 256>>>(out);
}

// round 5
// speedup vs baseline: 4.0227x; 1.3314x over previous
#include <cuda_runtime.h>
#include <cuda_fp16.h>
#include <math.h>
#include <stdint.h>

#define B_      4096
#define SEQ_    59
#define FEAT_   64
#define U_      1024
#define VOCAB_  578
#define NPAD    640
#define KTOT    1088            // U_ + FEAT_
#define N4U     4096            // 4*U_
#define XROW    (SEQ_*FEAT_)

#define KBLK        64
#define NKB         17          // KTOT / KBLK
#define NSTAGE      4
#define STAGE_BYTES 49152       // A 16K | Bhi 16K | Blo 16K
#define SMEM_BYTES  (NSTAGE * STAGE_BYTES)   // 196608

// ---------------- device scratch ----------------
__device__ __half g_Wt_hi[(size_t)N4U * KTOT];   // [n][k], n = 4u+g permuted
__device__ __half g_Wt_lo[(size_t)N4U * KTOT];
__device__ float  g_biasp[N4U];
__device__ __half g_h16[2][(size_t)B_ * U_];
__device__ float  g_hf32[(size_t)B_ * U_];       // fp32 h (for dense2)
__device__ float  g_c[(size_t)B_ * U_];
__device__ __half g_x16[(size_t)SEQ_ * B_ * FEAT_]; // [t][b][f]
__device__ float  g_w2p[U_ * NPAD];
__device__ float  g_b2p[NPAD];
__device__ float  g_logits[(size_t)B_ * NPAD];

// ---------------- helpers ----------------
__device__ __forceinline__ uint32_t s2u(const void* p) {
    uint32_t a;
    asm("{ .reg .u64 t; cvta.to.shared.u64 t, %1; cvt.u32.u64 %0, t; }"
        : "=r"(a) : "l"(p));
    return a;
}
__device__ __forceinline__ void cp16(uint32_t saddr, const void* g) {
    asm volatile("cp.async.cg.shared.global [%0], [%1], 16;"
                 :: "r"(saddr), "l"(g));
}
__device__ __forceinline__ void ldmx4(uint32_t* r, uint32_t addr) {
    asm volatile("ldmatrix.sync.aligned.m8n8.x4.shared.b16 {%0,%1,%2,%3}, [%4];"
                 : "=r"(r[0]), "=r"(r[1]), "=r"(r[2]), "=r"(r[3]) : "r"(addr));
}
__device__ __forceinline__ void mma_f16(float* d, const uint32_t* a,
                                        const uint32_t* b) {
    asm volatile(
        "mma.sync.aligned.m16n8k16.row.col.f32.f16.f16.f32 "
        "{%0,%1,%2,%3}, {%4,%5,%6,%7}, {%8,%9}, {%0,%1,%2,%3};"
        : "+f"(d[0]), "+f"(d[1]), "+f"(d[2]), "+f"(d[3])
        : "r"(a[0]), "r"(a[1]), "r"(a[2]), "r"(a[3]), "r"(b[0]), "r"(b[1]));
}
#define SWZ(o) ((o) ^ (((o) >> 3) & 0x70))

// ---------------- prep kernels ----------------
__global__ void prep_weights(const float* __restrict__ kernel,
                             const float* __restrict__ rec,
                             const float* __restrict__ bias,
                             const float* __restrict__ w2,
                             const float* __restrict__ b2) {
    int stride = gridDim.x * blockDim.x;
    int idx = blockIdx.x * blockDim.x + threadIdx.x;
    for (size_t i = idx; i < (size_t)N4U * KTOT; i += stride) {
        int n = (int)(i / KTOT), k = (int)(i % KTOT);
        int u = n >> 2, g = n & 3;
        int src = g * U_ + u;
        float v = (k < U_) ? rec[(size_t)k * N4U + src]
                           : kernel[(size_t)(k - U_) * N4U + src];
        __half h = __float2half(v);
        g_Wt_hi[i] = h;
        g_Wt_lo[i] = __float2half(v - __half2float(h));
    }
    for (int n = idx; n < N4U; n += stride) {
        int u = n >> 2, g = n & 3;
        g_biasp[n] = bias[g * U_ + u];
    }
    for (int i = idx; i < U_ * NPAD; i += stride) {
        int k = i / NPAD, v = i - k * NPAD;
        g_w2p[i] = (v < VOCAB_) ? w2[k * VOCAB_ + v] : 0.f;
    }
    for (int v = idx; v < NPAD; v += stride)
        g_b2p[v] = (v < VOCAB_) ? b2[v] : 0.f;
}

__global__ void prep_x(const float* __restrict__ x) {
    int stride = gridDim.x * blockDim.x;
    int idx = blockIdx.x * blockDim.x + threadIdx.x;
    for (size_t i = idx; i < (size_t)SEQ_ * B_ * FEAT_; i += stride) {
        int t = (int)(i / ((size_t)B_ * FEAT_));
        int r = (int)((i / FEAT_) % B_);
        int f = (int)(i % FEAT_);
        g_x16[i] = __float2half(x[(size_t)r * XROW + t * FEAT_ + f]);
    }
}

__global__ void zero_state() {
    int stride = gridDim.x * blockDim.x;
    int idx = blockIdx.x * blockDim.x + threadIdx.x;
    const __half z = __float2half(0.f);
    for (size_t i = idx; i < (size_t)B_ * U_; i += stride) {
        g_h16[0][i] = z;
        g_c[i] = 0.f;
    }
}

// ---------------- fused LSTM step: mma.sync fp16 2-pass (B split) ----------
// CTA 128x128, 8 warps (2M x 4N), warp tile 64x32, K-chunk 64,
// 4-stage cp.async, 1 barrier per K-block, fragment double-buffering.
__global__ void __launch_bounds__(256, 1)
lstm_step_mma(int t, int hin) {
    extern __shared__ __align__(1024) char smem[];
    const uint32_t sb = s2u(smem);
    const int tid = threadIdx.x;
    const int lane = tid & 31, wid = tid >> 5;
    const int wm = wid & 1, wn = wid >> 1;
    const int mbase = blockIdx.y * 128;
    const int nbase = blockIdx.x * 128;

    const __half* __restrict__ hh = g_h16[hin];
    __half* __restrict__ oh = g_h16[hin ^ 1];

    float acc[4][4][4];
    #pragma unroll
    for (int i = 0; i < 4; i++)
        #pragma unroll
        for (int j = 0; j < 4; j++)
            #pragma unroll
            for (int q = 0; q < 4; q++) acc[i][j][q] = 0.f;

    auto loadStage = [&](int s, int kb) {
        const uint32_t base = sb + s * STAGE_BYTES;
        #pragma unroll
        for (int it = 0; it < 4; it++) {
            int idx = tid + it * 256;
            int row = idx >> 3, cc = idx & 7;
            uint32_t sw = SWZ((uint32_t)(row * 128 + cc * 16));
            const __half* ga;
            if (kb < 16)
                ga = hh + (size_t)(mbase + row) * U_ + kb * KBLK + cc * 8;
            else
                ga = g_x16 + ((size_t)t * B_ + mbase + row) * FEAT_ + cc * 8;
            cp16(base + sw, ga);
            size_t ob = (size_t)(nbase + row) * KTOT + kb * KBLK + cc * 8;
            cp16(base + 16384 + sw, g_Wt_hi + ob);
            cp16(base + 32768 + sw, g_Wt_lo + ob);
        }
        asm volatile("cp.async.commit_group;" ::: "memory");
    };

    loadStage(0, 0);
    loadStage(1, 1);
    loadStage(2, 2);

    // fragment double buffers
    uint32_t af[2][4][4], bh[2][2][4], bl[2][2][4];
    const int arow = wm * 64 + (lane & 15);
    const int brow = wn * 32 + (lane & 7) + ((lane >> 4) & 1) * 8;

    for (int kb = 0; kb < NKB; kb++) {
        const int s = kb & 3;
        if (kb <= 14)      asm volatile("cp.async.wait_group 2;" ::: "memory");
        else if (kb == 15) asm volatile("cp.async.wait_group 1;" ::: "memory");
        else               asm volatile("cp.async.wait_group 0;" ::: "memory");
        __syncthreads();

        const uint32_t Ab = sb + s * STAGE_BYTES;
        const uint32_t Bh = Ab + 16384;
        const uint32_t Bl = Ab + 32768;

        auto loadFrags = [&](int kk, int buf) {
            const uint32_t akoff = (uint32_t)(kk * 32 + ((lane >> 4) & 1) * 16);
            #pragma unroll
            for (int mt = 0; mt < 4; mt++)
                ldmx4(af[buf][mt], Ab + SWZ((uint32_t)((arow + mt * 16) * 128) + akoff));
            const uint32_t bkoff = (uint32_t)(kk * 32 + ((lane >> 3) & 1) * 16);
            #pragma unroll
            for (int np = 0; np < 2; np++) {
                uint32_t adr = SWZ((uint32_t)((brow + np * 16) * 128) + bkoff);
                ldmx4(bh[buf][np], Bh + adr);
                ldmx4(bl[buf][np], Bl + adr);
            }
        };

        loadFrags(0, 0);
        // prefetch next stage's gmem loads right after barrier
        if (kb + 3 < NKB) loadStage((kb + 3) & 3, kb + 3);

        int cur = 0;
        #pragma unroll
        for (int kk = 0; kk < 4; kk++) {
            if (kk < 3) loadFrags(kk + 1, cur ^ 1);
            #pragma unroll
            for (int mt = 0; mt < 4; mt++)
                #pragma unroll
                for (int nt = 0; nt < 4; nt++) {
                    mma_f16(acc[mt][nt], af[cur][mt], &bh[cur][nt >> 1][(nt & 1) * 2]);
                    mma_f16(acc[mt][nt], af[cur][mt], &bl[cur][nt >> 1][(nt & 1) * 2]);
                }
            cur ^= 1;
        }
    }
    __syncthreads();

    // ---- epilogue: stage accums to smem [128][132], then gate math ----
    float* sf = reinterpret_cast<float*>(smem);
    #pragma unroll
    for (int mt = 0; mt < 4; mt++) {
        int r0 = wm * 64 + mt * 16 + (lane >> 2);
        #pragma unroll
        for (int nt = 0; nt < 4; nt++) {
            int c = wn * 32 + nt * 8 + 2 * (lane & 3);
            sf[r0 * 132 + c]           = acc[mt][nt][0];
            sf[r0 * 132 + c + 1]       = acc[mt][nt][1];
            sf[(r0 + 8) * 132 + c]     = acc[mt][nt][2];
            sf[(r0 + 8) * 132 + c + 1] = acc[mt][nt][3];
        }
    }
    __syncthreads();

    #pragma unroll 1
    for (int it = 0; it < 16; it++) {
        int idx = it * 256 + tid;
        int row = idx >> 5, uu = idx & 31;
        float4 z = *reinterpret_cast<const float4*>(&sf[row * 132 + uu * 4]);
        int n0 = nbase + uu * 4;
        float4 bz = *reinterpret_cast<const float4*>(&g_biasp[n0]);
        float zi = z.x + bz.x;
        float zf = z.y + bz.y;
        float zg = z.z + bz.z;
        float zo = z.w + bz.w;
        float ig = 1.f / (1.f + __expf(-zi));
        float fg = 1.f / (1.f + __expf(-zf));
        float gg = tanhf(zg);
        float og = 1.f / (1.f + __expf(-zo));
        size_t ci = (size_t)(mbase + row) * U_ + (n0 >> 2);
        float cn = fg * g_c[ci] + ig * gg;
        g_c[ci] = cn;
        float hv = og * tanhf(cn);
        oh[ci] = __float2half(hv);
        g_hf32[ci] = hv;
    }
}

// ---------------- final dense (fp32 SGEMM on fp32 h) ----------------
__global__ void __launch_bounds__(256, 2)
dense2() {
    const float* __restrict__ A = g_hf32;

    __shared__ __align__(16) float As[8][128];
    __shared__ __align__(16) float Bs[8][128];

    const int tid = threadIdx.x;
    const int tx = tid & 15, ty = tid >> 4;
    const int mbase = blockIdx.y * 128, nbase = blockIdx.x * 128;

    float acc[8][8];
    #pragma unroll
    for (int i = 0; i < 8; i++)
        #pragma unroll
        for (int j = 0; j < 8; j++) acc[i][j] = 0.f;

    const int arow = tid >> 1, acol = (tid & 1) << 2;
    const int brow = tid >> 5, bcol = (tid & 31) << 2;

    for (int k0 = 0; k0 < U_; k0 += 8) {
        float4 av = *reinterpret_cast<const float4*>(
            A + (size_t)(mbase + arow) * U_ + k0 + acol);
        As[acol + 0][arow] = av.x;
        As[acol + 1][arow] = av.y;
        As[acol + 2][arow] = av.z;
        As[acol + 3][arow] = av.w;

        float4 bv = *reinterpret_cast<const float4*>(
            g_w2p + (size_t)(k0 + brow) * NPAD + nbase + bcol);
        *reinterpret_cast<float4*>(&Bs[brow][bcol]) = bv;

        __syncthreads();
        #pragma unroll
        for (int kk = 0; kk < 8; kk++) {
            float a[8], b[8];
            const float4* Av = reinterpret_cast<const float4*>(&As[kk][ty * 8]);
            const float4* Bv = reinterpret_cast<const float4*>(&Bs[kk][tx * 8]);
            float4 a0 = Av[0], a1 = Av[1], b0 = Bv[0], b1 = Bv[1];
            a[0]=a0.x;a[1]=a0.y;a[2]=a0.z;a[3]=a0.w;a[4]=a1.x;a[5]=a1.y;a[6]=a1.z;a[7]=a1.w;
            b[0]=b0.x;b[1]=b0.y;b[2]=b0.z;b[3]=b0.w;b[4]=b1.x;b[5]=b1.y;b[6]=b1.z;b[7]=b1.w;
            #pragma unroll
            for (int i = 0; i < 8; i++)
                #pragma unroll
                for (int j = 0; j < 8; j++)
                    acc[i][j] = fmaf(a[i], b[j], acc[i][j]);
        }
        __syncthreads();
    }
    #pragma unroll
    for (int i = 0; i < 8; i++) {
        int bi = mbase + ty * 8 + i;
        #pragma unroll
        for (int j = 0; j < 8; j++) {
            int n = nbase + tx * 8 + j;
            g_logits[(size_t)bi * NPAD + n] = acc[i][j] + g_b2p[n];
        }
    }
}

// ---------------- softmax ----------------
__global__ void softmax_kernel(float* __restrict__ out) {
    const int b = blockIdx.x;
    const float* __restrict__ l = g_logits + (size_t)b * NPAD;
    __shared__ float red[256];
    const int tid = threadIdx.x;

    float mval = -1e30f;
    for (int v = tid; v < VOCAB_; v += 256) mval = fmaxf(mval, l[v]);
    red[tid] = mval;
    __syncthreads();
    for (int s = 128; s > 0; s >>= 1) {
        if (tid < s) red[tid] = fmaxf(red[tid], red[tid + s]);
        __syncthreads();
    }
    float mx = red[0];
    __syncthreads();

    float sum = 0.f;
    for (int v = tid; v < VOCAB_; v += 256) sum += expf(l[v] - mx);
    red[tid] = sum;
    __syncthreads();
    for (int s = 128; s > 0; s >>= 1) {
        if (tid < s) red[tid] += red[tid + s];
        __syncthreads();
    }
    float inv = 1.f / red[0];
    for (int v = tid; v < VOCAB_; v += 256)
        out[(size_t)b * VOCAB_ + v] = expf(l[v] - mx) * inv;
}

// ---------------- launch ----------------
extern "C" void kernel_launch(void* const* d_in, const int* in_sizes, int n_in,
                              void* d_out, int out_size) {
    const float* x      = (const float*)d_in[0];
    const float* kernel = (const float*)d_in[1];
    const float* rec    = (const float*)d_in[2];
    const float* bias   = (const float*)d_in[3];
    const float* w2     = (const float*)d_in[4];
    const float* b2     = (const float*)d_in[5];
    float* out = (float*)d_out;

    cudaFuncSetAttribute(lstm_step_mma,
                         cudaFuncAttributeMaxDynamicSharedMemorySize, SMEM_BYTES);

    prep_weights<<<2048, 256>>>(kernel, rec, bias, w2, b2);
    prep_x<<<2048, 256>>>(x);
    zero_state<<<2048, 256>>>();

    dim3 grid(N4U / 128, B_ / 128);   // 32 x 32
    for (int s = 0; s < SEQ_; s++)
        lstm_step_mma<<<grid, 256, SMEM_BYTES>>>(s, s & 1);

    dense2<<<dim3(NPAD / 128, B_ / 128), 256>>>();
    softmax_kernel<<<B_, 256>>>(out);
}

// round 6
// speedup vs baseline: 7.8804x; 1.9589x over previous
#include <cuda_runtime.h>
#include <cuda_fp16.h>
#include <math.h>
#include <stdint.h>

#define B_      4096
#define SEQ_    59
#define FEAT_   64
#define U_      1024
#define VOCAB_  578
#define NPAD    640
#define KTOT    1088            // U_ + FEAT_
#define N4U     4096            // 4*U_
#define XROW    (SEQ_*FEAT_)

#define KBLK        64
#define NKB         17          // KTOT / KBLK
#define NSTAGE      3
#define STAGE_BYTES 32768       // A 16K | B 16K
#define SMEM_BYTES  (NSTAGE * STAGE_BYTES)   // 98304 per CTA, 2 CTAs/SM

// ---------------- device scratch ----------------
__device__ __half g_Wt[(size_t)N4U * KTOT];      // [n][k], n = 4u+g permuted
__device__ float  g_biasp[N4U];
__device__ __half g_h16[2][(size_t)B_ * U_];
__device__ float  g_hf32[(size_t)B_ * U_];       // fp32 h (for dense2)
__device__ float  g_c[(size_t)B_ * U_];
__device__ __half g_x16[(size_t)SEQ_ * B_ * FEAT_]; // [t][b][f]
__device__ float  g_w2p[U_ * NPAD];
__device__ float  g_b2p[NPAD];
__device__ float  g_logits[(size_t)B_ * NPAD];

// ---------------- helpers ----------------
__device__ __forceinline__ uint32_t s2u(const void* p) {
    uint32_t a;
    asm("{ .reg .u64 t; cvta.to.shared.u64 t, %1; cvt.u32.u64 %0, t; }"
        : "=r"(a) : "l"(p));
    return a;
}
__device__ __forceinline__ void cp16(uint32_t saddr, const void* g) {
    asm volatile("cp.async.cg.shared.global [%0], [%1], 16;"
                 :: "r"(saddr), "l"(g));
}
__device__ __forceinline__ void ldmx4(uint32_t* r, uint32_t addr) {
    asm volatile("ldmatrix.sync.aligned.m8n8.x4.shared.b16 {%0,%1,%2,%3}, [%4];"
                 : "=r"(r[0]), "=r"(r[1]), "=r"(r[2]), "=r"(r[3]) : "r"(addr));
}
__device__ __forceinline__ void mma_f16(float* d, const uint32_t* a,
                                        const uint32_t* b) {
    asm volatile(
        "mma.sync.aligned.m16n8k16.row.col.f32.f16.f16.f32 "
        "{%0,%1,%2,%3}, {%4,%5,%6,%7}, {%8,%9}, {%0,%1,%2,%3};"
        : "+f"(d[0]), "+f"(d[1]), "+f"(d[2]), "+f"(d[3])
        : "r"(a[0]), "r"(a[1]), "r"(a[2]), "r"(a[3]), "r"(b[0]), "r"(b[1]));
}
#define SWZ(o) ((o) ^ (((o) >> 3) & 0x70))

// ---------------- prep kernels ----------------
__global__ void prep_weights(const float* __restrict__ kernel,
                             const float* __restrict__ rec,
                             const float* __restrict__ bias,
                             const float* __restrict__ w2,
                             const float* __restrict__ b2) {
    int stride = gridDim.x * blockDim.x;
    int idx = blockIdx.x * blockDim.x + threadIdx.x;
    for (size_t i = idx; i < (size_t)N4U * KTOT; i += stride) {
        int n = (int)(i / KTOT), k = (int)(i % KTOT);
        int u = n >> 2, g = n & 3;
        int src = g * U_ + u;
        float v = (k < U_) ? rec[(size_t)k * N4U + src]
                           : kernel[(size_t)(k - U_) * N4U + src];
        g_Wt[i] = __float2half(v);
    }
    for (int n = idx; n < N4U; n += stride) {
        int u = n >> 2, g = n & 3;
        g_biasp[n] = bias[g * U_ + u];
    }
    for (int i = idx; i < U_ * NPAD; i += stride) {
        int k = i / NPAD, v = i - k * NPAD;
        g_w2p[i] = (v < VOCAB_) ? w2[k * VOCAB_ + v] : 0.f;
    }
    for (int v = idx; v < NPAD; v += stride)
        g_b2p[v] = (v < VOCAB_) ? b2[v] : 0.f;
}

__global__ void prep_x(const float* __restrict__ x) {
    int stride = gridDim.x * blockDim.x;
    int idx = blockIdx.x * blockDim.x + threadIdx.x;
    for (size_t i = idx; i < (size_t)SEQ_ * B_ * FEAT_; i += stride) {
        int t = (int)(i / ((size_t)B_ * FEAT_));
        int r = (int)((i / FEAT_) % B_);
        int f = (int)(i % FEAT_);
        g_x16[i] = __float2half(x[(size_t)r * XROW + t * FEAT_ + f]);
    }
}

__global__ void zero_state() {
    int stride = gridDim.x * blockDim.x;
    int idx = blockIdx.x * blockDim.x + threadIdx.x;
    const __half z = __float2half(0.f);
    for (size_t i = idx; i < (size_t)B_ * U_; i += stride) {
        g_h16[0][i] = z;
        g_c[i] = 0.f;
    }
}

// ---------------- fused LSTM step: mma.sync fp16 single-pass --------------
// CTA 128x128, 8 warps (2M x 4N), warp tile 64x32, K-chunk 64,
// 3-stage cp.async, 1 barrier per K-block, 2 CTAs/SM.
__global__ void __launch_bounds__(256, 2)
lstm_step_mma(int t, int hin) {
    extern __shared__ __align__(1024) char smem[];
    const uint32_t sb = s2u(smem);
    const int tid = threadIdx.x;
    const int lane = tid & 31, wid = tid >> 5;
    const int wm = wid & 1, wn = wid >> 1;
    const int mbase = blockIdx.y * 128;
    const int nbase = blockIdx.x * 128;

    const __half* __restrict__ hh = g_h16[hin];
    __half* __restrict__ oh = g_h16[hin ^ 1];

    float acc[4][4][4];
    #pragma unroll
    for (int i = 0; i < 4; i++)
        #pragma unroll
        for (int j = 0; j < 4; j++)
            #pragma unroll
            for (int q = 0; q < 4; q++) acc[i][j][q] = 0.f;

    auto loadStage = [&](int s, int kb) {
        const uint32_t base = sb + s * STAGE_BYTES;
        #pragma unroll
        for (int it = 0; it < 4; it++) {
            int idx = tid + it * 256;
            int row = idx >> 3, cc = idx & 7;
            uint32_t sw = SWZ((uint32_t)(row * 128 + cc * 16));
            const __half* ga;
            if (kb < 16)
                ga = hh + (size_t)(mbase + row) * U_ + kb * KBLK + cc * 8;
            else
                ga = g_x16 + ((size_t)t * B_ + mbase + row) * FEAT_ + cc * 8;
            cp16(base + sw, ga);
            size_t ob = (size_t)(nbase + row) * KTOT + kb * KBLK + cc * 8;
            cp16(base + 16384 + sw, g_Wt + ob);
        }
        asm volatile("cp.async.commit_group;" ::: "memory");
    };

    loadStage(0, 0);
    loadStage(1, 1);

    const int arow = wm * 64 + (lane & 15);
    const int brow = wn * 32 + (lane & 7) + ((lane >> 4) & 1) * 8;

    for (int kb = 0; kb < NKB; kb++) {
        const int s = kb % 3;
        if (kb < NKB - 1) asm volatile("cp.async.wait_group 1;" ::: "memory");
        else             asm volatile("cp.async.wait_group 0;" ::: "memory");
        __syncthreads();

        // prefetch next stage's gmem loads right after barrier
        if (kb + 2 < NKB) loadStage((kb + 2) % 3, kb + 2);

        const uint32_t Ab = sb + s * STAGE_BYTES;
        const uint32_t Bb = Ab + 16384;

        #pragma unroll
        for (int kk = 0; kk < 4; kk++) {
            uint32_t af[4][4], bf[2][4];
            const uint32_t akoff = (uint32_t)(kk * 32 + ((lane >> 4) & 1) * 16);
            #pragma unroll
            for (int mt = 0; mt < 4; mt++)
                ldmx4(af[mt], Ab + SWZ((uint32_t)((arow + mt * 16) * 128) + akoff));
            const uint32_t bkoff = (uint32_t)(kk * 32 + ((lane >> 3) & 1) * 16);
            #pragma unroll
            for (int np = 0; np < 2; np++)
                ldmx4(bf[np], Bb + SWZ((uint32_t)((brow + np * 16) * 128) + bkoff));
            #pragma unroll
            for (int mt = 0; mt < 4; mt++)
                #pragma unroll
                for (int nt = 0; nt < 4; nt++)
                    mma_f16(acc[mt][nt], af[mt], &bf[nt >> 1][(nt & 1) * 2]);
        }
    }
    __syncthreads();

    // ---- epilogue: stage accums to smem [128][132], then gate math ----
    float* sf = reinterpret_cast<float*>(smem);
    #pragma unroll
    for (int mt = 0; mt < 4; mt++) {
        int r0 = wm * 64 + mt * 16 + (lane >> 2);
        #pragma unroll
        for (int nt = 0; nt < 4; nt++) {
            int c = wn * 32 + nt * 8 + 2 * (lane & 3);
            sf[r0 * 132 + c]           = acc[mt][nt][0];
            sf[r0 * 132 + c + 1]       = acc[mt][nt][1];
            sf[(r0 + 8) * 132 + c]     = acc[mt][nt][2];
            sf[(r0 + 8) * 132 + c + 1] = acc[mt][nt][3];
        }
    }
    __syncthreads();

    #pragma unroll 1
    for (int it = 0; it < 16; it++) {
        int idx = it * 256 + tid;
        int row = idx >> 5, uu = idx & 31;
        float4 z = *reinterpret_cast<const float4*>(&sf[row * 132 + uu * 4]);
        int n0 = nbase + uu * 4;
        float4 bz = *reinterpret_cast<const float4*>(&g_biasp[n0]);
        float zi = z.x + bz.x;
        float zf = z.y + bz.y;
        float zg = z.z + bz.z;
        float zo = z.w + bz.w;
        float ig = 1.f / (1.f + __expf(-zi));
        float fg = 1.f / (1.f + __expf(-zf));
        float gg = tanhf(zg);
        float og = 1.f / (1.f + __expf(-zo));
        size_t ci = (size_t)(mbase + row) * U_ + (n0 >> 2);
        float cn = fg * g_c[ci] + ig * gg;
        g_c[ci] = cn;
        float hv = og * tanhf(cn);
        oh[ci] = __float2half(hv);
        g_hf32[ci] = hv;
    }
}

// ---------------- final dense (fp32 SGEMM on fp32 h) ----------------
__global__ void __launch_bounds__(256, 2)
dense2() {
    const float* __restrict__ A = g_hf32;

    __shared__ __align__(16) float As[8][128];
    __shared__ __align__(16) float Bs[8][128];

    const int tid = threadIdx.x;
    const int tx = tid & 15, ty = tid >> 4;
    const int mbase = blockIdx.y * 128, nbase = blockIdx.x * 128;

    float acc[8][8];
    #pragma unroll
    for (int i = 0; i < 8; i++)
        #pragma unroll
        for (int j = 0; j < 8; j++) acc[i][j] = 0.f;

    const int arow = tid >> 1, acol = (tid & 1) << 2;
    const int brow = tid >> 5, bcol = (tid & 31) << 2;

    for (int k0 = 0; k0 < U_; k0 += 8) {
        float4 av = *reinterpret_cast<const float4*>(
            A + (size_t)(mbase + arow) * U_ + k0 + acol);
        As[acol + 0][arow] = av.x;
        As[acol + 1][arow] = av.y;
        As[acol + 2][arow] = av.z;
        As[acol + 3][arow] = av.w;

        float4 bv = *reinterpret_cast<const float4*>(
            g_w2p + (size_t)(k0 + brow) * NPAD + nbase + bcol);
        *reinterpret_cast<float4*>(&Bs[brow][bcol]) = bv;

        __syncthreads();
        #pragma unroll
        for (int kk = 0; kk < 8; kk++) {
            float a[8], b[8];
            const float4* Av = reinterpret_cast<const float4*>(&As[kk][ty * 8]);
            const float4* Bv = reinterpret_cast<const float4*>(&Bs[kk][tx * 8]);
            float4 a0 = Av[0], a1 = Av[1], b0 = Bv[0], b1 = Bv[1];
            a[0]=a0.x;a[1]=a0.y;a[2]=a0.z;a[3]=a0.w;a[4]=a1.x;a[5]=a1.y;a[6]=a1.z;a[7]=a1.w;
            b[0]=b0.x;b[1]=b0.y;b[2]=b0.z;b[3]=b0.w;b[4]=b1.x;b[5]=b1.y;b[6]=b1.z;b[7]=b1.w;
            #pragma unroll
            for (int i = 0; i < 8; i++)
                #pragma unroll
                for (int j = 0; j < 8; j++)
                    acc[i][j] = fmaf(a[i], b[j], acc[i][j]);
        }
        __syncthreads();
    }
    #pragma unroll
    for (int i = 0; i < 8; i++) {
        int bi = mbase + ty * 8 + i;
        #pragma unroll
        for (int j = 0; j < 8; j++) {
            int n = nbase + tx * 8 + j;
            g_logits[(size_t)bi * NPAD + n] = acc[i][j] + g_b2p[n];
        }
    }
}

// ---------------- softmax ----------------
__global__ void softmax_kernel(float* __restrict__ out) {
    const int b = blockIdx.x;
    const float* __restrict__ l = g_logits + (size_t)b * NPAD;
    __shared__ float red[256];
    const int tid = threadIdx.x;

    float mval = -1e30f;
    for (int v = tid; v < VOCAB_; v += 256) mval = fmaxf(mval, l[v]);
    red[tid] = mval;
    __syncthreads();
    for (int s = 128; s > 0; s >>= 1) {
        if (tid < s) red[tid] = fmaxf(red[tid], red[tid + s]);
        __syncthreads();
    }
    float mx = red[0];
    __syncthreads();

    float sum = 0.f;
    for (int v = tid; v < VOCAB_; v += 256) sum += expf(l[v] - mx);
    red[tid] = sum;
    __syncthreads();
    for (int s = 128; s > 0; s >>= 1) {
        if (tid < s) red[tid] += red[tid + s];
        __syncthreads();
    }
    float inv = 1.f / red[0];
    for (int v = tid; v < VOCAB_; v += 256)
        out[(size_t)b * VOCAB_ + v] = expf(l[v] - mx) * inv;
}

// ---------------- launch ----------------
extern "C" void kernel_launch(void* const* d_in, const int* in_sizes, int n_in,
                              void* d_out, int out_size) {
    const float* x      = (const float*)d_in[0];
    const float* kernel = (const float*)d_in[1];
    const float* rec    = (const float*)d_in[2];
    const float* bias   = (const float*)d_in[3];
    const float* w2     = (const float*)d_in[4];
    const float* b2     = (const float*)d_in[5];
    float* out = (float*)d_out;

    cudaFuncSetAttribute(lstm_step_mma,
                         cudaFuncAttributeMaxDynamicSharedMemorySize, SMEM_BYTES);

    prep_weights<<<2048, 256>>>(kernel, rec, bias, w2, b2);
    prep_x<<<2048, 256>>>(x);
    zero_state<<<2048, 256>>>();

    dim3 grid(N4U / 128, B_ / 128);   // 32 x 32
    for (int s = 0; s < SEQ_; s++)
        lstm_step_mma<<<grid, 256, SMEM_BYTES>>>(s, s & 1);

    dense2<<<dim3(NPAD / 128, B_ / 128), 256>>>();
    softmax_kernel<<<B_, 256>>>(out);
}

// round 7
// speedup vs baseline: 8.5362x; 1.0832x over previous
#include <cuda_runtime.h>
#include <cuda_fp16.h>
#include <math.h>
#include <stdint.h>

#define B_      4096
#define SEQ_    59
#define FEAT_   64
#define U_      1024
#define VOCAB_  578
#define NPAD    640
#define KTOT    1088            // U_ + FEAT_
#define N4U     4096            // 4*U_
#define XROW    (SEQ_*FEAT_)

#define KBLK        64
#define NKB         17          // KTOT / KBLK
#define NSTAGE      3
#define STAGE_BYTES 32768       // A 16K | B 16K
#define SMEM_BYTES  (NSTAGE * STAGE_BYTES)   // 98304 per CTA, 2 CTAs/SM

// ---------------- device scratch ----------------
__device__ __half g_Wt[(size_t)N4U * KTOT];      // [n][k], n = 4u+g permuted
__device__ float  g_biasp[N4U];
__device__ __half g_h16[2][(size_t)B_ * U_];
__device__ float  g_hf32[(size_t)B_ * U_];       // fp32 h (for dense2)
__device__ float  g_c[(size_t)B_ * U_];
__device__ __half g_x16[(size_t)SEQ_ * B_ * FEAT_]; // [t][b][f]
__device__ float  g_w2p[U_ * NPAD];
__device__ float  g_b2p[NPAD];
__device__ float  g_logits[(size_t)B_ * NPAD];

// ---------------- helpers ----------------
__device__ __forceinline__ uint32_t s2u(const void* p) {
    uint32_t a;
    asm("{ .reg .u64 t; cvta.to.shared.u64 t, %1; cvt.u32.u64 %0, t; }"
        : "=r"(a) : "l"(p));
    return a;
}
__device__ __forceinline__ void cp16(uint32_t saddr, const void* g) {
    asm volatile("cp.async.cg.shared.global [%0], [%1], 16;"
                 :: "r"(saddr), "l"(g));
}
__device__ __forceinline__ void ldmx4(uint32_t* r, uint32_t addr) {
    asm volatile("ldmatrix.sync.aligned.m8n8.x4.shared.b16 {%0,%1,%2,%3}, [%4];"
                 : "=r"(r[0]), "=r"(r[1]), "=r"(r[2]), "=r"(r[3]) : "r"(addr));
}
__device__ __forceinline__ void mma_f16(float* d, const uint32_t* a,
                                        const uint32_t* b) {
    asm volatile(
        "mma.sync.aligned.m16n8k16.row.col.f32.f16.f16.f32 "
        "{%0,%1,%2,%3}, {%4,%5,%6,%7}, {%8,%9}, {%0,%1,%2,%3};"
        : "+f"(d[0]), "+f"(d[1]), "+f"(d[2]), "+f"(d[3])
        : "r"(a[0]), "r"(a[1]), "r"(a[2]), "r"(a[3]), "r"(b[0]), "r"(b[1]));
}
#define SWZ(o) ((o) ^ (((o) >> 3) & 0x70))

__device__ __forceinline__ float fast_sigmoid(float x) {
    return __fdividef(1.f, 1.f + __expf(-x));
}
__device__ __forceinline__ float fast_tanh(float x) {
    float e = __expf(2.f * x);
    return 1.f - __fdividef(2.f, e + 1.f);
}

// ---------------- prep kernels ----------------
__global__ void prep_weights(const float* __restrict__ kernel,
                             const float* __restrict__ rec,
                             const float* __restrict__ bias,
                             const float* __restrict__ w2,
                             const float* __restrict__ b2) {
    int stride = gridDim.x * blockDim.x;
    int idx = blockIdx.x * blockDim.x + threadIdx.x;
    for (size_t i = idx; i < (size_t)N4U * KTOT; i += stride) {
        int n = (int)(i / KTOT), k = (int)(i % KTOT);
        int u = n >> 2, g = n & 3;
        int src = g * U_ + u;
        float v = (k < U_) ? rec[(size_t)k * N4U + src]
                           : kernel[(size_t)(k - U_) * N4U + src];
        g_Wt[i] = __float2half(v);
    }
    for (int n = idx; n < N4U; n += stride) {
        int u = n >> 2, g = n & 3;
        g_biasp[n] = bias[g * U_ + u];
    }
    for (int i = idx; i < U_ * NPAD; i += stride) {
        int k = i / NPAD, v = i - k * NPAD;
        g_w2p[i] = (v < VOCAB_) ? w2[k * VOCAB_ + v] : 0.f;
    }
    for (int v = idx; v < NPAD; v += stride)
        g_b2p[v] = (v < VOCAB_) ? b2[v] : 0.f;
}

__global__ void prep_x(const float* __restrict__ x) {
    int stride = gridDim.x * blockDim.x;
    int idx = blockIdx.x * blockDim.x + threadIdx.x;
    for (size_t i = idx; i < (size_t)SEQ_ * B_ * FEAT_; i += stride) {
        int t = (int)(i / ((size_t)B_ * FEAT_));
        int r = (int)((i / FEAT_) % B_);
        int f = (int)(i % FEAT_);
        g_x16[i] = __float2half(x[(size_t)r * XROW + t * FEAT_ + f]);
    }
}

__global__ void zero_state() {
    int stride = gridDim.x * blockDim.x;
    int idx = blockIdx.x * blockDim.x + threadIdx.x;
    const __half z = __float2half(0.f);
    for (size_t i = idx; i < (size_t)B_ * U_; i += stride) {
        g_h16[0][i] = z;
        g_c[i] = 0.f;
    }
}

// ---------------- fused LSTM step: mma.sync fp16 single-pass --------------
// CTA 128x128, 8 warps (2M x 4N), warp tile 64x32, K-chunk 64,
// 3-stage cp.async, 1 barrier per K-block, 2 CTAs/SM,
// per-warp kk rotation to decorrelate ldmatrix/MMA phases.
__global__ void __launch_bounds__(256, 2)
lstm_step_mma(int t, int hin) {
    extern __shared__ __align__(1024) char smem[];
    const uint32_t sb = s2u(smem);
    const int tid = threadIdx.x;
    const int lane = tid & 31, wid = tid >> 5;
    const int wm = wid & 1, wn = wid >> 1;
    const int mbase = blockIdx.y * 128;
    const int nbase = blockIdx.x * 128;

    const __half* __restrict__ hh = g_h16[hin];
    __half* __restrict__ oh = g_h16[hin ^ 1];

    float acc[4][4][4];
    #pragma unroll
    for (int i = 0; i < 4; i++)
        #pragma unroll
        for (int j = 0; j < 4; j++)
            #pragma unroll
            for (int q = 0; q < 4; q++) acc[i][j][q] = 0.f;

    auto loadStage = [&](int s, int kb) {
        const uint32_t base = sb + s * STAGE_BYTES;
        #pragma unroll
        for (int it = 0; it < 4; it++) {
            int idx = tid + it * 256;
            int row = idx >> 3, cc = idx & 7;
            uint32_t sw = SWZ((uint32_t)(row * 128 + cc * 16));
            const __half* ga;
            if (kb < 16)
                ga = hh + (size_t)(mbase + row) * U_ + kb * KBLK + cc * 8;
            else
                ga = g_x16 + ((size_t)t * B_ + mbase + row) * FEAT_ + cc * 8;
            cp16(base + sw, ga);
            size_t ob = (size_t)(nbase + row) * KTOT + kb * KBLK + cc * 8;
            cp16(base + 16384 + sw, g_Wt + ob);
        }
        asm volatile("cp.async.commit_group;" ::: "memory");
    };

    loadStage(0, 0);
    loadStage(1, 1);

    const int arow = wm * 64 + (lane & 15);
    const int brow = wn * 32 + (lane & 7) + ((lane >> 4) & 1) * 8;

    for (int kb = 0; kb < NKB; kb++) {
        const int s = kb % 3;
        if (kb < NKB - 1) asm volatile("cp.async.wait_group 1;" ::: "memory");
        else             asm volatile("cp.async.wait_group 0;" ::: "memory");
        __syncthreads();

        // prefetch next stage's gmem loads right after barrier
        if (kb + 2 < NKB) loadStage((kb + 2) % 3, kb + 2);

        const uint32_t Ab = sb + s * STAGE_BYTES;
        const uint32_t Bb = Ab + 16384;

        #pragma unroll
        for (int kx = 0; kx < 4; kx++) {
            // rotate kk per warp: decorrelates ldmatrix vs MMA phases
            const int kk = (kx + wid) & 3;
            uint32_t af[4][4], bf[2][4];
            const uint32_t akoff = (uint32_t)(kk * 32 + ((lane >> 4) & 1) * 16);
            #pragma unroll
            for (int mt = 0; mt < 4; mt++)
                ldmx4(af[mt], Ab + SWZ((uint32_t)((arow + mt * 16) * 128) + akoff));
            const uint32_t bkoff = (uint32_t)(kk * 32 + ((lane >> 3) & 1) * 16);
            #pragma unroll
            for (int np = 0; np < 2; np++)
                ldmx4(bf[np], Bb + SWZ((uint32_t)((brow + np * 16) * 128) + bkoff));
            #pragma unroll
            for (int mt = 0; mt < 4; mt++)
                #pragma unroll
                for (int nt = 0; nt < 4; nt++)
                    mma_f16(acc[mt][nt], af[mt], &bf[nt >> 1][(nt & 1) * 2]);
        }
    }
    __syncthreads();

    // ---- epilogue: stage accums to smem [128][132], then gate math ----
    float* sf = reinterpret_cast<float*>(smem);
    #pragma unroll
    for (int mt = 0; mt < 4; mt++) {
        int r0 = wm * 64 + mt * 16 + (lane >> 2);
        #pragma unroll
        for (int nt = 0; nt < 4; nt++) {
            int c = wn * 32 + nt * 8 + 2 * (lane & 3);
            sf[r0 * 132 + c]           = acc[mt][nt][0];
            sf[r0 * 132 + c + 1]       = acc[mt][nt][1];
            sf[(r0 + 8) * 132 + c]     = acc[mt][nt][2];
            sf[(r0 + 8) * 132 + c + 1] = acc[mt][nt][3];
        }
    }
    __syncthreads();

    #pragma unroll 1
    for (int it = 0; it < 16; it++) {
        int idx = it * 256 + tid;
        int row = idx >> 5, uu = idx & 31;
        float4 z = *reinterpret_cast<const float4*>(&sf[row * 132 + uu * 4]);
        int n0 = nbase + uu * 4;
        float4 bz = *reinterpret_cast<const float4*>(&g_biasp[n0]);
        float ig = fast_sigmoid(z.x + bz.x);
        float fg = fast_sigmoid(z.y + bz.y);
        float gg = fast_tanh(z.z + bz.z);
        float og = fast_sigmoid(z.w + bz.w);
        size_t ci = (size_t)(mbase + row) * U_ + (n0 >> 2);
        float cn = fg * g_c[ci] + ig * gg;
        g_c[ci] = cn;
        float hv = og * fast_tanh(cn);
        oh[ci] = __float2half(hv);
        g_hf32[ci] = hv;
    }
}

// ---------------- final dense (fp32 SGEMM on fp32 h) ----------------
__global__ void __launch_bounds__(256, 2)
dense2() {
    const float* __restrict__ A = g_hf32;

    __shared__ __align__(16) float As[8][128];
    __shared__ __align__(16) float Bs[8][128];

    const int tid = threadIdx.x;
    const int tx = tid & 15, ty = tid >> 4;
    const int mbase = blockIdx.y * 128, nbase = blockIdx.x * 128;

    float acc[8][8];
    #pragma unroll
    for (int i = 0; i < 8; i++)
        #pragma unroll
        for (int j = 0; j < 8; j++) acc[i][j] = 0.f;

    const int arow = tid >> 1, acol = (tid & 1) << 2;
    const int brow = tid >> 5, bcol = (tid & 31) << 2;

    for (int k0 = 0; k0 < U_; k0 += 8) {
        float4 av = *reinterpret_cast<const float4*>(
            A + (size_t)(mbase + arow) * U_ + k0 + acol);
        As[acol + 0][arow] = av.x;
        As[acol + 1][arow] = av.y;
        As[acol + 2][arow] = av.z;
        As[acol + 3][arow] = av.w;

        float4 bv = *reinterpret_cast<const float4*>(
            g_w2p + (size_t)(k0 + brow) * NPAD + nbase + bcol);
        *reinterpret_cast<float4*>(&Bs[brow][bcol]) = bv;

        __syncthreads();
        #pragma unroll
        for (int kk = 0; kk < 8; kk++) {
            float a[8], b[8];
            const float4* Av = reinterpret_cast<const float4*>(&As[kk][ty * 8]);
            const float4* Bv = reinterpret_cast<const float4*>(&Bs[kk][tx * 8]);
            float4 a0 = Av[0], a1 = Av[1], b0 = Bv[0], b1 = Bv[1];
            a[0]=a0.x;a[1]=a0.y;a[2]=a0.z;a[3]=a0.w;a[4]=a1.x;a[5]=a1.y;a[6]=a1.z;a[7]=a1.w;
            b[0]=b0.x;b[1]=b0.y;b[2]=b0.z;b[3]=b0.w;b[4]=b1.x;b[5]=b1.y;b[6]=b1.z;b[7]=b1.w;
            #pragma unroll
            for (int i = 0; i < 8; i++)
                #pragma unroll
                for (int j = 0; j < 8; j++)
                    acc[i][j] = fmaf(a[i], b[j], acc[i][j]);
        }
        __syncthreads();
    }
    #pragma unroll
    for (int i = 0; i < 8; i++) {
        int bi = mbase + ty * 8 + i;
        #pragma unroll
        for (int j = 0; j < 8; j++) {
            int n = nbase + tx * 8 + j;
            g_logits[(size_t)bi * NPAD + n] = acc[i][j] + g_b2p[n];
        }
    }
}

// ---------------- softmax ----------------
__global__ void softmax_kernel(float* __restrict__ out) {
    const int b = blockIdx.x;
    const float* __restrict__ l = g_logits + (size_t)b * NPAD;
    __shared__ float red[256];
    const int tid = threadIdx.x;

    float mval = -1e30f;
    for (int v = tid; v < VOCAB_; v += 256) mval = fmaxf(mval, l[v]);
    red[tid] = mval;
    __syncthreads();
    for (int s = 128; s > 0; s >>= 1) {
        if (tid < s) red[tid] = fmaxf(red[tid], red[tid + s]);
        __syncthreads();
    }
    float mx = red[0];
    __syncthreads();

    float sum = 0.f;
    for (int v = tid; v < VOCAB_; v += 256) sum += expf(l[v] - mx);
    red[tid] = sum;
    __syncthreads();
    for (int s = 128; s > 0; s >>= 1) {
        if (tid < s) red[tid] += red[tid + s];
        __syncthreads();
    }
    float inv = 1.f / red[0];
    for (int v = tid; v < VOCAB_; v += 256)
        out[(size_t)b * VOCAB_ + v] = expf(l[v] - mx) * inv;
}

// ---------------- launch ----------------
extern "C" void kernel_launch(void* const* d_in, const int* in_sizes, int n_in,
                              void* d_out, int out_size) {
    const float* x      = (const float*)d_in[0];
    const float* kernel = (const float*)d_in[1];
    const float* rec    = (const float*)d_in[2];
    const float* bias   = (const float*)d_in[3];
    const float* w2     = (const float*)d_in[4];
    const float* b2     = (const float*)d_in[5];
    float* out = (float*)d_out;

    cudaFuncSetAttribute(lstm_step_mma,
                         cudaFuncAttributeMaxDynamicSharedMemorySize, SMEM_BYTES);

    prep_weights<<<2048, 256>>>(kernel, rec, bias, w2, b2);
    prep_x<<<2048, 256>>>(x);
    zero_state<<<2048, 256>>>();

    dim3 grid(N4U / 128, B_ / 128);   // 32 x 32
    for (int s = 0; s < SEQ_; s++)
        lstm_step_mma<<<grid, 256, SMEM_BYTES>>>(s, s & 1);

    dense2<<<dim3(NPAD / 128, B_ / 128), 256>>>();
    softmax_kernel<<<B_, 256>>>(out);
}